// round 1
// baseline (speedup 1.0000x reference)
#include <cuda_runtime.h>
#include <cuda_bf16.h>
#include <math.h>

// Problem shape (fixed by reference setup_inputs)
#define Nn 4096
#define Tt 64
#define Dd 1024
#define THREADS 256          // 8 warps
#define CACHE_ROWS 24        // rows of h[n] cached in SMEM for pass B

// Dynamic smem layout (floats):
//   [0, 1024)        w_score
//   [1024, 1088)     scores[64]
//   [1088, 1152)     alpha[64]
//   [1152, 1152+CACHE_ROWS*1024)  cached h rows
#define SMEM_FLOATS (1152 + CACHE_ROWS * Dd)
#define SMEM_BYTES  (SMEM_FLOATS * 4)

__global__ __launch_bounds__(THREADS, 2)
void attn_pool_kernel(const float* __restrict__ h,
                      const float* __restrict__ w_score,
                      float* __restrict__ out_pooled,
                      float* __restrict__ out_alpha)
{
    extern __shared__ float smem[];
    float* wsh     = smem;               // 1024
    float* scores  = smem + 1024;        // 64
    float* alpha_s = smem + 1088;        // 64
    float* cache   = smem + 1152;        // CACHE_ROWS*1024

    const int n    = blockIdx.x;
    const int tid  = threadIdx.x;
    const int warp = tid >> 5;
    const int lane = tid & 31;

    const float* hrow = h + (size_t)n * (Tt * Dd);

    // Load w_score into smem (float4)
    {
        const float4* w4 = (const float4*)w_score;
        float4* wsh4 = (float4*)wsh;
        wsh4[tid] = w4[tid];             // 256 threads * 16B = 4KB exactly
    }
    __syncthreads();

    // ---------------- Pass A: scores[t] = dot(h[n,t,:], w) ----------------
    const float4* wsh4 = (const float4*)wsh;
    float4* cache4 = (float4*)cache;

    for (int t = warp; t < Tt; t += 8) {
        const float4* r = (const float4*)(hrow + (size_t)t * Dd);
        float acc = 0.0f;
        #pragma unroll
        for (int j = 0; j < 8; j++) {
            const int idx = lane + 32 * j;      // 256 float4 per row
            float4 v  = r[idx];
            float4 wv = wsh4[idx];
            if (t < CACHE_ROWS) cache4[t * 256 + idx] = v;
            acc += v.x * wv.x + v.y * wv.y + v.z * wv.z + v.w * wv.w;
        }
        #pragma unroll
        for (int off = 16; off > 0; off >>= 1)
            acc += __shfl_xor_sync(0xFFFFFFFFu, acc, off);
        if (lane == 0) scores[t] = acc;
    }
    __syncthreads();

    // ---------------- Softmax over T=64 (redundant per-thread) ----------------
    float m = -INFINITY;
    #pragma unroll
    for (int t = 0; t < Tt; t++) m = fmaxf(m, scores[t]);
    float s = 0.0f;
    #pragma unroll
    for (int t = 0; t < Tt; t++) s += __expf(scores[t] - m);
    const float inv_s = 1.0f / s;

    if (tid < Tt) {
        float a = __expf(scores[tid] - m) * inv_s;
        alpha_s[tid] = a;
        out_alpha[(size_t)n * Tt + tid] = a;
    }
    __syncthreads();

    // ---------------- Pass B: pooled[d] = sum_t alpha[t] * h[n,t,d] ----------------
    // Thread tid owns float4 at d-offset tid*4 (256*4 = 1024 = D exactly).
    const float4* col = (const float4*)hrow + tid;   // stride 256 float4 per t
    float4 acc = make_float4(0.f, 0.f, 0.f, 0.f);

    #pragma unroll
    for (int t = 0; t < CACHE_ROWS; t++) {
        float a = alpha_s[t];
        float4 v = cache4[t * 256 + tid];
        acc.x += a * v.x; acc.y += a * v.y; acc.z += a * v.z; acc.w += a * v.w;
    }
    #pragma unroll 8
    for (int t = CACHE_ROWS; t < Tt; t++) {
        float a = alpha_s[t];
        float4 v = col[(size_t)t * 256];
        acc.x += a * v.x; acc.y += a * v.y; acc.z += a * v.z; acc.w += a * v.w;
    }

    ((float4*)(out_pooled + (size_t)n * Dd))[tid] = acc;
}

extern "C" void kernel_launch(void* const* d_in, const int* in_sizes, int n_in,
                              void* d_out, int out_size)
{
    const float* h       = (const float*)d_in[0];   // [N, T, D] fp32
    const float* w_score = (const float*)d_in[1];   // [D] fp32

    float* out        = (float*)d_out;
    float* out_pooled = out;                        // [N, D]
    float* out_alpha  = out + (size_t)Nn * Dd;      // [N, T]

    cudaFuncSetAttribute(attn_pool_kernel,
                         cudaFuncAttributeMaxDynamicSharedMemorySize, SMEM_BYTES);

    attn_pool_kernel<<<Nn, THREADS, SMEM_BYTES>>>(h, w_score, out_pooled, out_alpha);
}

// round 3
// speedup vs baseline: 1.3865x; 1.3865x over previous
#include <cuda_runtime.h>
#include <cuda_bf16.h>
#include <math.h>

// Shape fixed by reference: N=4096, T=64, D=1024, fp32.
#define Nn 4096
#define Tt 64
#define Dd 1024
#define THREADS 256        // 8 warps; thread tid owns float4 at d-offset 4*tid
#define TILE 8             // t-rows per tile; Tt/TILE = 8 tiles

// Static smem: part[t][w] partial dots (64 x 8 floats) = 2 KB
__global__ __launch_bounds__(THREADS, 3)
void attn_pool_onepass(const float* __restrict__ h,
                       const float* __restrict__ w_score,
                       float* __restrict__ out_pooled,
                       float* __restrict__ out_alpha)
{
    __shared__ float part[Tt * 8];   // part[t*8 + warp]

    const int n    = blockIdx.x;
    const int tid  = threadIdx.x;
    const int warp = tid >> 5;
    const int lane = tid & 31;

    const float4* base = (const float4*)(h + (size_t)n * (Tt * Dd)) + tid; // col slice, stride 256
    const float4  wv   = __ldg((const float4*)w_score + tid);

    float m = -INFINITY;
    float Z = 0.0f;
    float4 acc = make_float4(0.f, 0.f, 0.f, 0.f);

    #pragma unroll 1
    for (int tt = 0; tt < Tt / TILE; tt++) {
        // ---- load 8-row slab (front-batched LDG.128) ----
        float4 v[TILE];
        #pragma unroll
        for (int i = 0; i < TILE; i++)
            v[i] = base[(size_t)(tt * TILE + i) * 256];

        // ---- partial dots vs w (this thread's 4 d-values) ----
        float pd[TILE];
        #pragma unroll
        for (int i = 0; i < TILE; i++)
            pd[i] = v[i].x * wv.x + v[i].y * wv.y + v[i].z * wv.z + v[i].w * wv.w;

        // ---- warp reduce each of the 8 partials (warp covers 128 contiguous d) ----
        #pragma unroll
        for (int i = 0; i < TILE; i++) {
            #pragma unroll
            for (int off = 16; off > 0; off >>= 1)
                pd[i] += __shfl_xor_sync(0xFFFFFFFFu, pd[i], off);
        }
        if (lane < TILE)  // lane i writes pd[i]? no — need per-i; use lane0 loop-free trick:
            ;
        if (lane == 0) {
            #pragma unroll
            for (int i = 0; i < TILE; i++)
                part[(tt * TILE + i) * 8 + warp] = pd[i];
        }
        __syncthreads();

        // ---- every thread assembles the 8 scores (broadcast LDS) ----
        float s[TILE];
        #pragma unroll
        for (int i = 0; i < TILE; i++) {
            float acc_s = 0.0f;
            #pragma unroll
            for (int w = 0; w < 8; w++)
                acc_s += part[(tt * TILE + i) * 8 + w];
            s[i] = acc_s;
        }

        // ---- online softmax update using register-resident slab ----
        float tmax = s[0];
        #pragma unroll
        for (int i = 1; i < TILE; i++) tmax = fmaxf(tmax, s[i]);
        float newm  = fmaxf(m, tmax);
        float scale = __expf(m - newm);
        Z *= scale;
        acc.x *= scale; acc.y *= scale; acc.z *= scale; acc.w *= scale;
        #pragma unroll
        for (int i = 0; i < TILE; i++) {
            float e = __expf(s[i] - newm);
            Z += e;
            acc.x += e * v[i].x; acc.y += e * v[i].y;
            acc.z += e * v[i].z; acc.w += e * v[i].w;
        }
        m = newm;
    }

    const float inv = 1.0f / Z;

    // pooled: thread's float4
    float4 outv = make_float4(acc.x * inv, acc.y * inv, acc.z * inv, acc.w * inv);
    ((float4*)(out_pooled + (size_t)n * Dd))[tid] = outv;

    // alpha: threads 0..63 recompute score t from persistent part[][]
    if (tid < Tt) {
        float sc = 0.0f;
        #pragma unroll
        for (int w = 0; w < 8; w++)
            sc += part[tid * 8 + w];
        out_alpha[(size_t)n * Tt + tid] = __expf(sc - m) * inv;
    }
}

extern "C" void kernel_launch(void* const* d_in, const int* in_sizes, int n_in,
                              void* d_out, int out_size)
{
    const float* h       = (const float*)d_in[0];   // [N, T, D] fp32
    const float* w_score = (const float*)d_in[1];   // [D] fp32

    float* out        = (float*)d_out;
    float* out_pooled = out;                        // [N, D]
    float* out_alpha  = out + (size_t)Nn * Dd;      // [N, T]

    attn_pool_onepass<<<Nn, THREADS>>>(h, w_score, out_pooled, out_alpha);
}

// round 4
// speedup vs baseline: 1.3873x; 1.0006x over previous
#include <cuda_runtime.h>
#include <cuda_bf16.h>
#include <cstdint>
#include <math.h>

// Shape fixed by reference: N=4096, T=64, D=1024, fp32.
#define Nn 4096
#define Tt 64
#define Dd 1024
#define THREADS 256          // thread tid owns float4 at d-offset 4*tid
#define TILE 8               // t-rows per tile (32 KB contiguous chunk of h[n])
#define NTILES (Tt / TILE)   // 8
#define TILE_BYTES (TILE * Dd * 4)   // 32768
#define NBUF 2

// smem layout (bytes):
//   [0,16)        mbar[2]
//   [16,2064)     part[Tt*8] partial dots
//   [2064,2064+2*32768) buffers (16B aligned: 2064 = 129*16)
#define SMEM_MBAR_OFF 0
#define SMEM_PART_OFF 16
#define SMEM_BUF_OFF  2064
#define SMEM_BYTES    (SMEM_BUF_OFF + NBUF * TILE_BYTES)   // 67600

__device__ __forceinline__ uint32_t smem_u32(const void* p) {
    uint32_t a;
    asm("{ .reg .u64 t; cvta.to.shared.u64 t, %1; cvt.u32.u64 %0, t; }" : "=r"(a) : "l"(p));
    return a;
}

__device__ __forceinline__ void mbar_init(uint32_t mbar, uint32_t count) {
    asm volatile("mbarrier.init.shared.b64 [%0], %1;" :: "r"(mbar), "r"(count) : "memory");
}
__device__ __forceinline__ void mbar_expect_tx(uint32_t mbar, uint32_t bytes) {
    asm volatile("mbarrier.arrive.expect_tx.shared.b64 _, [%0], %1;" :: "r"(mbar), "r"(bytes) : "memory");
}
__device__ __forceinline__ void bulk_copy_g2s(uint32_t dst_smem, const void* src_gmem,
                                              uint32_t bytes, uint32_t mbar) {
    asm volatile(
        "cp.async.bulk.shared::cluster.global.mbarrier::complete_tx::bytes [%0], [%1], %2, [%3];"
        :: "r"(dst_smem), "l"(src_gmem), "r"(bytes), "r"(mbar) : "memory");
}
__device__ __forceinline__ void mbar_wait_parity(uint32_t mbar, uint32_t parity) {
    uint32_t done;
    asm volatile(
        "{\n\t.reg .pred p;\n\t"
        "mbarrier.try_wait.parity.acquire.cta.shared::cta.b64 p, [%1], %2;\n\t"
        "selp.b32 %0, 1, 0, p;\n\t}"
        : "=r"(done) : "r"(mbar), "r"(parity) : "memory");
    if (!done) {
        asm volatile(
            "{\n\t.reg .pred P1;\n\t"
            "WL_%=:\n\t"
            "mbarrier.try_wait.parity.acquire.cta.shared::cta.b64 P1, [%0], %1, 0x989680;\n\t"
            "@P1 bra.uni WD_%=;\n\t"
            "bra.uni WL_%=;\n\t"
            "WD_%=:\n\t}"
            :: "r"(mbar), "r"(parity) : "memory");
    }
}

__global__ __launch_bounds__(THREADS, 3)
void attn_pool_async(const float* __restrict__ h,
                     const float* __restrict__ w_score,
                     float* __restrict__ out_pooled,
                     float* __restrict__ out_alpha)
{
    extern __shared__ __align__(16) char smem_raw[];
    float*  part = (float*)(smem_raw + SMEM_PART_OFF);       // part[t*8 + warp]
    const uint32_t mbar0 = smem_u32(smem_raw + SMEM_MBAR_OFF);
    const uint32_t mbar1 = mbar0 + 8;
    const uint32_t buf_s = smem_u32(smem_raw + SMEM_BUF_OFF);
    const float4* buf0 = (const float4*)(smem_raw + SMEM_BUF_OFF);
    const float4* buf1 = (const float4*)(smem_raw + SMEM_BUF_OFF + TILE_BYTES);

    const int n    = blockIdx.x;
    const int tid  = threadIdx.x;
    const int warp = tid >> 5;
    const int lane = tid & 31;

    const char* src = (const char*)(h + (size_t)n * (Tt * Dd));
    const float4 wv = __ldg((const float4*)w_score + tid);

    if (tid == 0) {
        mbar_init(mbar0, 1);
        mbar_init(mbar1, 1);
    }
    __syncthreads();
    if (tid == 0) {
        mbar_expect_tx(mbar0, TILE_BYTES);
        bulk_copy_g2s(buf_s, src, TILE_BYTES, mbar0);
        mbar_expect_tx(mbar1, TILE_BYTES);
        bulk_copy_g2s(buf_s + TILE_BYTES, src + TILE_BYTES, TILE_BYTES, mbar1);
    }

    float m = -INFINITY;
    float Z = 0.0f;
    float4 acc = make_float4(0.f, 0.f, 0.f, 0.f);

    #pragma unroll
    for (int tt = 0; tt < NTILES; tt++) {
        const int b        = tt & 1;
        const uint32_t mb  = b ? mbar1 : mbar0;
        const uint32_t par = (tt >> 1) & 1;          // k-th reuse parity
        const float4* bp   = b ? buf1 : buf0;

        mbar_wait_parity(mb, par);

        // ---- pull slab into regs (one LDS.128 x 8, conflict-free) ----
        float4 v[TILE];
        #pragma unroll
        for (int i = 0; i < TILE; i++)
            v[i] = bp[i * 256 + tid];

        // ---- partial dots, warp reduce, store to part ----
        float pd[TILE];
        #pragma unroll
        for (int i = 0; i < TILE; i++)
            pd[i] = v[i].x * wv.x + v[i].y * wv.y + v[i].z * wv.z + v[i].w * wv.w;
        #pragma unroll
        for (int i = 0; i < TILE; i++) {
            #pragma unroll
            for (int off = 16; off > 0; off >>= 1)
                pd[i] += __shfl_xor_sync(0xFFFFFFFFu, pd[i], off);
        }
        if (lane == 0) {
            #pragma unroll
            for (int i = 0; i < TILE; i++)
                part[(tt * TILE + i) * 8 + warp] = pd[i];
        }
        __syncthreads();   // part ready AND slab fully consumed into regs

        // ---- immediately refill this buffer for tile tt+2 ----
        if (tid == 0 && tt + 2 < NTILES) {
            mbar_expect_tx(mb, TILE_BYTES);
            bulk_copy_g2s(buf_s + b * TILE_BYTES,
                          src + (size_t)(tt + 2) * TILE_BYTES, TILE_BYTES, mb);
        }

        // ---- assemble scores (broadcast LDS) ----
        float s[TILE];
        #pragma unroll
        for (int i = 0; i < TILE; i++) {
            float a = 0.0f;
            #pragma unroll
            for (int w = 0; w < 8; w++)
                a += part[(tt * TILE + i) * 8 + w];
            s[i] = a;
        }

        // ---- online softmax update (slab in regs) ----
        float tmax = s[0];
        #pragma unroll
        for (int i = 1; i < TILE; i++) tmax = fmaxf(tmax, s[i]);
        float newm  = fmaxf(m, tmax);
        float scale = __expf(m - newm);
        Z *= scale;
        acc.x *= scale; acc.y *= scale; acc.z *= scale; acc.w *= scale;
        #pragma unroll
        for (int i = 0; i < TILE; i++) {
            float e = __expf(s[i] - newm);
            Z += e;
            acc.x += e * v[i].x; acc.y += e * v[i].y;
            acc.z += e * v[i].z; acc.w += e * v[i].w;
        }
        m = newm;
    }

    const float inv = 1.0f / Z;

    ((float4*)(out_pooled + (size_t)n * Dd))[tid] =
        make_float4(acc.x * inv, acc.y * inv, acc.z * inv, acc.w * inv);

    if (tid < Tt) {
        float sc = 0.0f;
        #pragma unroll
        for (int w = 0; w < 8; w++)
            sc += part[tid * 8 + w];
        out_alpha[(size_t)n * Tt + tid] = __expf(sc - m) * inv;
    }
}

extern "C" void kernel_launch(void* const* d_in, const int* in_sizes, int n_in,
                              void* d_out, int out_size)
{
    const float* h       = (const float*)d_in[0];   // [N, T, D] fp32
    const float* w_score = (const float*)d_in[1];   // [D] fp32

    float* out        = (float*)d_out;
    float* out_pooled = out;                        // [N, D]
    float* out_alpha  = out + (size_t)Nn * Dd;      // [N, T]

    cudaFuncSetAttribute(attn_pool_async,
                         cudaFuncAttributeMaxDynamicSharedMemorySize, SMEM_BYTES);

    attn_pool_async<<<Nn, THREADS, SMEM_BYTES>>>(h, w_score, out_pooled, out_alpha);
}